// round 2
// baseline (speedup 1.0000x reference)
#include <cuda_runtime.h>
#include <math_constants.h>

#define BB   32
#define HH   32
#define DD   128
#define KVHH 8
#define GG   4      // GQA group
#define PP   2048
#define TT   64
#define PPS  64
#define SEQ  4096

#define NSPLIT 8
#define WARPS  4
#define PARTS  (NSPLIT*WARPS)        // 32 partials per (b,kvh)
#define CHUNK  (SEQ/NSPLIT)          // 512 tokens
#define PGC    (CHUNK/TT)            // 8 pages per chunk
#define MLSZ   (1+GG)                // per-partial record: m, l0..l3

// Scratch for split-KV partials (no runtime allocation allowed)
__device__ float g_acc[BB*KVHH*PARTS*GG*DD];   // ~16.8 MB
__device__ float g_ml [BB*KVHH*PARTS*MLSZ];

__global__ void __launch_bounds__(WARPS*32, 8)
pa_partial(const float* __restrict__ q,
           const float* __restrict__ kp,
           const float* __restrict__ vp,
           const int*   __restrict__ lengths,
           const int*   __restrict__ pidx)
{
    const int bid   = blockIdx.x;
    const int split = bid % NSPLIT;
    const int kvh   = (bid / NSPLIT) % KVHH;
    const int b     = bid / (NSPLIT*KVHH);
    const int tid   = threadIdx.x;
    const int warp  = tid >> 5;
    const int lane  = tid & 31;

    __shared__ int pg[PGC];
    __shared__ int s_len;
    if (tid < PGC) pg[tid] = pidx[b*PPS + split*PGC + tid];
    if (tid == 0)  s_len = lengths[b];
    __syncthreads();
    const int len = s_len;

    // Per-lane Q slices: 4 heads x float4 at d = lane*4
    float4 q4[GG];
#pragma unroll
    for (int g = 0; g < GG; g++)
        q4[g] = *(const float4*)(q + (size_t)((b*HH + kvh*GG + g)*DD) + lane*4);

    float m = -CUDART_INF_F;
    float l[GG];
    float4 acc[GG];
#pragma unroll
    for (int g = 0; g < GG; g++) {
        l[g] = 0.f;
        acc[g] = make_float4(0.f, 0.f, 0.f, 0.f);
    }

    const int c0 = split * CHUNK;
    const int c1 = min(c0 + CHUNK, len);

    const float* __restrict__ kb = kp + (size_t)kvh * PP * TT * DD;
    const float* __restrict__ vb = vp + (size_t)kvh * PP * TT * DD;

    int s = c0 + warp;
    float4 k4, v4;
    if (s < c1) {
        int page = pg[(s >> 6) & 7];
        size_t off = ((size_t)page * TT + (s & 63)) * DD + lane * 4;
        k4 = *(const float4*)(kb + off);
        v4 = *(const float4*)(vb + off);
    }

    for (; s < c1; s += WARPS) {
        // prefetch next token's K/V (breaks DRAM latency off the softmax chain)
        float4 k4n, v4n;
        const int sn = s + WARPS;
        if (sn < c1) {
            int page = pg[(sn >> 6) & 7];
            size_t off = ((size_t)page * TT + (sn & 63)) * DD + lane * 4;
            k4n = *(const float4*)(kb + off);
            v4n = *(const float4*)(vb + off);
        }

        // partial dots: 4 heads x 4 elems per lane, butterfly-reduce to full dot
        float s0 = q4[0].x*k4.x + q4[0].y*k4.y + q4[0].z*k4.z + q4[0].w*k4.w;
        float s1 = q4[1].x*k4.x + q4[1].y*k4.y + q4[1].z*k4.z + q4[1].w*k4.w;
        float s2 = q4[2].x*k4.x + q4[2].y*k4.y + q4[2].z*k4.z + q4[2].w*k4.w;
        float s3 = q4[3].x*k4.x + q4[3].y*k4.y + q4[3].z*k4.z + q4[3].w*k4.w;
#pragma unroll
        for (int o = 16; o; o >>= 1) {
            s0 += __shfl_xor_sync(0xffffffffu, s0, o);
            s1 += __shfl_xor_sync(0xffffffffu, s1, o);
            s2 += __shfl_xor_sync(0xffffffffu, s2, o);
            s3 += __shfl_xor_sync(0xffffffffu, s3, o);
        }

        const float smax = fmaxf(fmaxf(s0, s1), fmaxf(s2, s3));
        if (smax > m) {                        // warp-uniform, rare after warmup
            const float alpha = __expf(m - smax);
#pragma unroll
            for (int g = 0; g < GG; g++) {
                l[g] *= alpha;
                acc[g].x *= alpha; acc[g].y *= alpha;
                acc[g].z *= alpha; acc[g].w *= alpha;
            }
            m = smax;
        }
        float w[GG];
        w[0] = __expf(s0 - m);
        w[1] = __expf(s1 - m);
        w[2] = __expf(s2 - m);
        w[3] = __expf(s3 - m);
#pragma unroll
        for (int g = 0; g < GG; g++) {
            l[g] += w[g];                      // PER-HEAD partition function
            acc[g].x += w[g] * v4.x;
            acc[g].y += w[g] * v4.y;
            acc[g].z += w[g] * v4.z;
            acc[g].w += w[g] * v4.w;
        }

        k4 = k4n; v4 = v4n;
    }

    // write this warp's partial (always, even if empty: m=-inf, l=0, acc=0)
    const int part = split * WARPS + warp;
    float* outp = g_acc + (size_t)(((b*KVHH + kvh)*PARTS + part)*GG) * DD + lane*4;
#pragma unroll
    for (int g = 0; g < GG; g++)
        *(float4*)(outp + g*DD) = acc[g];
    if (lane == 0) {
        const int mi = ((b*KVHH + kvh)*PARTS + part) * MLSZ;
        g_ml[mi + 0] = m;
#pragma unroll
        for (int g = 0; g < GG; g++)
            g_ml[mi + 1 + g] = l[g];
    }
}

__global__ void __launch_bounds__(DD)
pa_combine(float* __restrict__ out)
{
    const int bh  = blockIdx.x;          // b*H + h
    const int b   = bh / HH;
    const int h   = bh % HH;
    const int kvh = h / GG;
    const int g   = h % GG;
    const int d   = threadIdx.x;         // 128 threads = D

    __shared__ float sm[PARTS], sl[PARTS];
    if (d < PARTS) {
        const int mi = ((b*KVHH + kvh)*PARTS + d) * MLSZ;
        sm[d] = g_ml[mi + 0];
        sl[d] = g_ml[mi + 1 + g];        // this head's partition function
    }
    __syncthreads();

    float M = -CUDART_INF_F;
#pragma unroll
    for (int p = 0; p < PARTS; p++) M = fmaxf(M, sm[p]);

    float L = 0.f, o = 0.f;
    const float* base = g_acc + (size_t)((b*KVHH + kvh)*PARTS) * GG * DD + g*DD + d;
#pragma unroll 4
    for (int p = 0; p < PARTS; p++) {
        const float e = __expf(sm[p] - M);
        L += e * sl[p];
        o += e * base[(size_t)p * GG * DD];
    }
    out[(size_t)bh * DD + d] = o / L;
}

extern "C" void kernel_launch(void* const* d_in, const int* in_sizes, int n_in,
                              void* d_out, int out_size)
{
    const float* q   = (const float*)d_in[0];
    const float* kpg = (const float*)d_in[1];
    const float* vpg = (const float*)d_in[2];
    const int*   len = (const int*)  d_in[3];
    const int*   pid = (const int*)  d_in[4];
    float* out = (float*)d_out;

    pa_partial<<<BB*KVHH*NSPLIT, WARPS*32>>>(q, kpg, vpg, len, pid);
    pa_combine<<<BB*HH, DD>>>(out);
}

// round 3
// speedup vs baseline: 1.0566x; 1.0566x over previous
#include <cuda_runtime.h>
#include <math_constants.h>

typedef unsigned long long u64;

#define BB   32
#define HH   32
#define DD   128
#define KVHH 8
#define GG   4      // GQA group
#define PP   2048
#define TT   64
#define PPS  64
#define SEQ  4096

#define NSPLIT 8
#define WARPS  4
#define PARTS  (NSPLIT*WARPS)        // 32 partials per (b,kvh)
#define CHUNK  (SEQ/NSPLIT)          // 512 tokens
#define PGC    (CHUNK/TT)            // 8 pages per chunk
#define MLSZ   (1+GG)                // per-partial record: m, l0..l3

// packed fp32x2 math (PTX-only; ptxas never auto-fuses these)
#define FMA2(d,a,b,c) asm("fma.rn.f32x2 %0, %1, %2, %3;" : "=l"(d) : "l"(a), "l"(b), "l"(c))
#define MUL2(d,a,b)   asm("mul.rn.f32x2 %0, %1, %2;"     : "=l"(d) : "l"(a), "l"(b))
#define ADD2(d,a,b)   asm("add.rn.f32x2 %0, %1, %2;"     : "=l"(d) : "l"(a), "l"(b))

__device__ __forceinline__ float hadd2(u64 v) {
    float2 f = *reinterpret_cast<float2*>(&v);
    return f.x + f.y;
}
__device__ __forceinline__ u64 pack2(float x) {
    float2 f = make_float2(x, x);
    return *reinterpret_cast<u64*>(&f);
}

// Scratch for split-KV partials (no runtime allocation allowed)
__device__ float g_acc[BB*KVHH*PARTS*GG*DD];   // ~16.8 MB
__device__ float g_ml [BB*KVHH*PARTS*MLSZ];

__global__ void __launch_bounds__(WARPS*32, 4)
pa_partial(const float* __restrict__ q,
           const float* __restrict__ kp,
           const float* __restrict__ vp,
           const int*   __restrict__ lengths,
           const int*   __restrict__ pidx)
{
    const int bid   = blockIdx.x;
    const int split = bid % NSPLIT;
    const int kvh   = (bid / NSPLIT) % KVHH;
    const int b     = bid / (NSPLIT*KVHH);
    const int tid   = threadIdx.x;
    const int warp  = tid >> 5;
    const int lane  = tid & 31;
    const int lig   = lane & 15;      // lane-in-group: covers dims lig*4..+3 and +64..
    const int grp   = lane >> 4;      // 2 tokens per warp-iteration

    __shared__ int pg[PGC];
    __shared__ int s_len;
    if (tid < PGC) pg[tid] = pidx[b*PPS + split*PGC + tid];
    if (tid == 0)  s_len = lengths[b];
    __syncthreads();
    const int len = s_len;

    // Q packed as f32x2 pairs: 4 heads x 4 pairs (8 dims per lane)
    u64 qp[GG][4];
#pragma unroll
    for (int g = 0; g < GG; g++) {
        const float* qh = q + (size_t)((b*HH + kvh*GG + g)*DD) + lig*4;
        ulonglong2 a  = *(const ulonglong2*)qh;
        ulonglong2 b2 = *(const ulonglong2*)(qh + 64);
        qp[g][0] = a.x;  qp[g][1] = a.y;
        qp[g][2] = b2.x; qp[g][3] = b2.y;
    }

    float m = -CUDART_INF_F;
    float l[GG];
    u64 acc[GG][4];
#pragma unroll
    for (int g = 0; g < GG; g++) {
        l[g] = 0.f;
#pragma unroll
        for (int p = 0; p < 4; p++) acc[g][p] = 0ull;
    }

    const int c0 = split * CHUNK;
    const int c1 = min(c0 + CHUNK, len);

    const float* __restrict__ kb = kp + (size_t)kvh * PP * TT * DD + lig*4;
    const float* __restrict__ vb = vp + (size_t)kvh * PP * TT * DD + lig*4;

    int tok = c0 + warp*2 + grp;
    ulonglong2 kA, kB, vA, vB;
    if (tok < c1) {
        int page = pg[(tok >> 6) & (PGC-1)];
        size_t off = ((size_t)page * TT + (tok & 63)) * DD;
        kA = *(const ulonglong2*)(kb + off);
        kB = *(const ulonglong2*)(kb + off + 64);
        vA = *(const ulonglong2*)(vb + off);
        vB = *(const ulonglong2*)(vb + off + 64);
    }

    for (int base = c0 + warp*2; base < c1; base += WARPS*2) {
        // prefetch next pair of tokens
        const int tokn = tok + WARPS*2;
        ulonglong2 kAn, kBn, vAn, vBn;
        if (tokn < c1) {
            int page = pg[(tokn >> 6) & (PGC-1)];
            size_t off = ((size_t)page * TT + (tokn & 63)) * DD;
            kAn = *(const ulonglong2*)(kb + off);
            kBn = *(const ulonglong2*)(kb + off + 64);
            vAn = *(const ulonglong2*)(vb + off);
            vBn = *(const ulonglong2*)(vb + off + 64);
        }

        // dots in packed pairs: 4 heads x 4 f32x2-FMA
        u64 d2[GG];
#pragma unroll
        for (int g = 0; g < GG; g++) {
            MUL2(d2[g], qp[g][0], kA.x);
            FMA2(d2[g], qp[g][1], kA.y, d2[g]);
            FMA2(d2[g], qp[g][2], kB.x, d2[g]);
            FMA2(d2[g], qp[g][3], kB.y, d2[g]);
        }
        float s0 = hadd2(d2[0]);
        float s1 = hadd2(d2[1]);
        float s2 = hadd2(d2[2]);
        float s3 = hadd2(d2[3]);
#pragma unroll
        for (int o = 8; o; o >>= 1) {      // reduce within 16-lane group
            s0 += __shfl_xor_sync(0xffffffffu, s0, o);
            s1 += __shfl_xor_sync(0xffffffffu, s1, o);
            s2 += __shfl_xor_sync(0xffffffffu, s2, o);
            s3 += __shfl_xor_sync(0xffffffffu, s3, o);
        }

        if (tok < c1) {                    // group-uniform predicate
            const float smax = fmaxf(fmaxf(s0, s1), fmaxf(s2, s3));
            if (smax > m) {                // rare after warmup
                const float alpha = __expf(m - smax);
                const u64 a2 = pack2(alpha);
#pragma unroll
                for (int g = 0; g < GG; g++) {
                    l[g] *= alpha;
#pragma unroll
                    for (int p = 0; p < 4; p++) MUL2(acc[g][p], acc[g][p], a2);
                }
                m = smax;
            }
            float w[GG];
            w[0] = __expf(s0 - m);
            w[1] = __expf(s1 - m);
            w[2] = __expf(s2 - m);
            w[3] = __expf(s3 - m);
#pragma unroll
            for (int g = 0; g < GG; g++) {
                l[g] += w[g];
                const u64 w2 = pack2(w[g]);
                FMA2(acc[g][0], w2, vA.x, acc[g][0]);
                FMA2(acc[g][1], w2, vA.y, acc[g][1]);
                FMA2(acc[g][2], w2, vB.x, acc[g][2]);
                FMA2(acc[g][3], w2, vB.y, acc[g][3]);
            }
        }

        kA = kAn; kB = kBn; vA = vAn; vB = vBn;
        tok = tokn;
    }

    // merge the two 16-lane groups within the warp
    {
        const float mo = __shfl_xor_sync(0xffffffffu, m, 16);
        const float M  = fmaxf(m, mo);
        const float sc = (m == M) ? 1.f : __expf(m - M);   // handles -inf==-inf
        const u64 sc2 = pack2(sc);
#pragma unroll
        for (int g = 0; g < GG; g++) {
            const float ls = l[g] * sc;
            l[g] = ls + __shfl_xor_sync(0xffffffffu, ls, 16);
#pragma unroll
            for (int p = 0; p < 4; p++) {
                u64 t; MUL2(t, acc[g][p], sc2);
                u64 o = __shfl_xor_sync(0xffffffffu, t, 16);
                ADD2(acc[g][p], t, o);
            }
        }
        m = M;
    }

    // one partial per warp (PARTS = NSPLIT*WARPS = 32, unchanged)
    const int part = split * WARPS + warp;
    if (lane < 16) {
        float* outp = g_acc + (size_t)(((b*KVHH + kvh)*PARTS + part)*GG) * DD + lig*4;
#pragma unroll
        for (int g = 0; g < GG; g++) {
            *(ulonglong2*)(outp + g*DD)      = make_ulonglong2(acc[g][0], acc[g][1]);
            *(ulonglong2*)(outp + g*DD + 64) = make_ulonglong2(acc[g][2], acc[g][3]);
        }
    }
    if (lane == 0) {
        const int mi = ((b*KVHH + kvh)*PARTS + part) * MLSZ;
        g_ml[mi + 0] = m;
#pragma unroll
        for (int g = 0; g < GG; g++) g_ml[mi + 1 + g] = l[g];
    }
}

__global__ void __launch_bounds__(DD)
pa_combine(float* __restrict__ out)
{
    const int bh  = blockIdx.x;          // b*H + h
    const int b   = bh / HH;
    const int h   = bh % HH;
    const int kvh = h / GG;
    const int g   = h % GG;
    const int d   = threadIdx.x;         // 128 threads = D

    __shared__ float sm[PARTS], sl[PARTS];
    if (d < PARTS) {
        const int mi = ((b*KVHH + kvh)*PARTS + d) * MLSZ;
        sm[d] = g_ml[mi + 0];
        sl[d] = g_ml[mi + 1 + g];        // this head's partition function
    }
    __syncthreads();

    float M = -CUDART_INF_F;
#pragma unroll
    for (int p = 0; p < PARTS; p++) M = fmaxf(M, sm[p]);

    // 4 independent accumulator chains for MLP
    float L0 = 0.f, L1 = 0.f, L2 = 0.f, L3 = 0.f;
    float o0 = 0.f, o1 = 0.f, o2 = 0.f, o3 = 0.f;
    const float* base = g_acc + (size_t)((b*KVHH + kvh)*PARTS) * GG * DD + g*DD + d;
#pragma unroll
    for (int p = 0; p < PARTS; p += 4) {
        const float e0 = __expf(sm[p+0] - M);
        const float e1 = __expf(sm[p+1] - M);
        const float e2 = __expf(sm[p+2] - M);
        const float e3 = __expf(sm[p+3] - M);
        L0 += e0 * sl[p+0];  o0 += e0 * base[(size_t)(p+0) * GG * DD];
        L1 += e1 * sl[p+1];  o1 += e1 * base[(size_t)(p+1) * GG * DD];
        L2 += e2 * sl[p+2];  o2 += e2 * base[(size_t)(p+2) * GG * DD];
        L3 += e3 * sl[p+3];  o3 += e3 * base[(size_t)(p+3) * GG * DD];
    }
    out[(size_t)bh * DD + d] = ((o0 + o1) + (o2 + o3)) / ((L0 + L1) + (L2 + L3));
}

extern "C" void kernel_launch(void* const* d_in, const int* in_sizes, int n_in,
                              void* d_out, int out_size)
{
    const float* q   = (const float*)d_in[0];
    const float* kpg = (const float*)d_in[1];
    const float* vpg = (const float*)d_in[2];
    const int*   len = (const int*)  d_in[3];
    const int*   pid = (const int*)  d_in[4];
    float* out = (float*)d_out;

    pa_partial<<<BB*KVHH*NSPLIT, WARPS*32>>>(q, kpg, vpg, len, pid);
    pa_combine<<<BB*HH, DD>>>(out);
}

// round 7
// speedup vs baseline: 1.0724x; 1.0149x over previous
#include <cuda_runtime.h>
#include <math_constants.h>

typedef unsigned long long u64;

#define BB   32
#define HH   32
#define DD   128
#define KVHH 8
#define GG   4      // GQA group
#define PP   2048
#define TT   64
#define PPS  64
#define SEQ  4096

#define NSPLIT 8
#define WARPS  4
#define PARTS  (NSPLIT*WARPS)        // 32 partials per (b,kvh)
#define CHUNK  (SEQ/NSPLIT)          // 512 tokens
#define PGC    (CHUNK/TT)            // 8 pages per chunk
#define MLSZ   (1+GG)                // per-partial record: m, l0..l3

// packed fp32x2 math (PTX-only; ptxas never auto-fuses these)
#define FMA2(d,a,b,c) asm("fma.rn.f32x2 %0, %1, %2, %3;" : "=l"(d) : "l"(a), "l"(b), "l"(c))
#define MUL2(d,a,b)   asm("mul.rn.f32x2 %0, %1, %2;"     : "=l"(d) : "l"(a), "l"(b))
#define ADD2(d,a,b)   asm("add.rn.f32x2 %0, %1, %2;"     : "=l"(d) : "l"(a), "l"(b))

__device__ __forceinline__ float hadd2(u64 v) {
    float2 f = *reinterpret_cast<float2*>(&v);
    return f.x + f.y;
}
__device__ __forceinline__ u64 pack2(float x) {
    float2 f = make_float2(x, x);
    return *reinterpret_cast<u64*>(&f);
}

// Scratch for split-KV partials (no runtime allocation allowed)
__device__ float g_acc[BB*KVHH*PARTS*GG*DD];   // ~16.8 MB
__device__ float g_ml [BB*KVHH*PARTS*MLSZ];

struct KVRegs { ulonglong2 kA, kB, vA, vB; };

__global__ void pa_nop() {}

__global__ void __launch_bounds__(WARPS*32, 3)
pa_partial(const float* __restrict__ q,
           const float* __restrict__ kp,
           const float* __restrict__ vp,
           const int*   __restrict__ lengths,
           const int*   __restrict__ pidx)
{
    const int bid   = blockIdx.x;
    const int split = bid % NSPLIT;
    const int kvh   = (bid / NSPLIT) % KVHH;
    const int b     = bid / (NSPLIT*KVHH);
    const int tid   = threadIdx.x;
    const int warp  = tid >> 5;
    const int lane  = tid & 31;
    const int lig   = lane & 15;      // lane-in-group: covers dims lig*4..+3 and +64..
    const int grp   = lane >> 4;      // 2 tokens per warp-iteration

    __shared__ int pg[PGC];
    __shared__ int s_len;
    if (tid < PGC) pg[tid] = pidx[b*PPS + split*PGC + tid];
    if (tid == 0)  s_len = lengths[b];
    __syncthreads();
    const int len = s_len;

    // Q packed as f32x2 pairs: 4 heads x 4 pairs (8 dims per lane)
    u64 qp[GG][4];
#pragma unroll
    for (int g = 0; g < GG; g++) {
        const float* qh = q + (size_t)((b*HH + kvh*GG + g)*DD) + lig*4;
        ulonglong2 a  = *(const ulonglong2*)qh;
        ulonglong2 b2 = *(const ulonglong2*)(qh + 64);
        qp[g][0] = a.x;  qp[g][1] = a.y;
        qp[g][2] = b2.x; qp[g][3] = b2.y;
    }

    float m = -CUDART_INF_F;
    float l[GG];
    u64 acc[GG][4];
#pragma unroll
    for (int g = 0; g < GG; g++) {
        l[g] = 0.f;
#pragma unroll
        for (int p = 0; p < 4; p++) acc[g][p] = 0ull;
    }

    const int c0 = split * CHUNK;
    const int c1 = min(c0 + CHUNK, len);

    const float* __restrict__ kb = kp + (size_t)kvh * PP * TT * DD + lig*4;
    const float* __restrict__ vb = vp + (size_t)kvh * PP * TT * DD + lig*4;

    auto ldkv = [&](int t, KVRegs& r) {
        if (t < c1) {
            int page = pg[(t >> 6) & (PGC-1)];
            size_t off = ((size_t)page * TT + (t & 63)) * DD;
            r.kA = *(const ulonglong2*)(kb + off);
            r.kB = *(const ulonglong2*)(kb + off + 64);
            r.vA = *(const ulonglong2*)(vb + off);
            r.vB = *(const ulonglong2*)(vb + off + 64);
        }
    };

    auto step = [&](const KVRegs& r, int t) {
        u64 d2[GG];
#pragma unroll
        for (int g = 0; g < GG; g++) {
            MUL2(d2[g], qp[g][0], r.kA.x);
            FMA2(d2[g], qp[g][1], r.kA.y, d2[g]);
            FMA2(d2[g], qp[g][2], r.kB.x, d2[g]);
            FMA2(d2[g], qp[g][3], r.kB.y, d2[g]);
        }
        float s0 = hadd2(d2[0]);
        float s1 = hadd2(d2[1]);
        float s2 = hadd2(d2[2]);
        float s3 = hadd2(d2[3]);
#pragma unroll
        for (int o = 8; o; o >>= 1) {      // reduce within 16-lane group
            s0 += __shfl_xor_sync(0xffffffffu, s0, o);
            s1 += __shfl_xor_sync(0xffffffffu, s1, o);
            s2 += __shfl_xor_sync(0xffffffffu, s2, o);
            s3 += __shfl_xor_sync(0xffffffffu, s3, o);
        }

        if (t < c1) {                      // group-uniform predicate
            const float smax = fmaxf(fmaxf(s0, s1), fmaxf(s2, s3));
            if (smax > m) {                // rare after warmup
                const float alpha = __expf(m - smax);
                const u64 a2 = pack2(alpha);
#pragma unroll
                for (int g = 0; g < GG; g++) {
                    l[g] *= alpha;
#pragma unroll
                    for (int p = 0; p < 4; p++) MUL2(acc[g][p], acc[g][p], a2);
                }
                m = smax;
            }
            float w[GG];
            w[0] = __expf(s0 - m);
            w[1] = __expf(s1 - m);
            w[2] = __expf(s2 - m);
            w[3] = __expf(s3 - m);
#pragma unroll
            for (int g = 0; g < GG; g++) {
                l[g] += w[g];
                const u64 w2 = pack2(w[g]);
                FMA2(acc[g][0], w2, r.vA.x, acc[g][0]);
                FMA2(acc[g][1], w2, r.vA.y, acc[g][1]);
                FMA2(acc[g][2], w2, r.vB.x, acc[g][2]);
                FMA2(acc[g][3], w2, r.vB.y, acc[g][3]);
            }
        }
    };

    // 2-deep software pipeline, unrolled by 2 half-iterations
    int base = c0 + warp*2;
    KVRegs b0, b1;
    ldkv(base + grp,     b0);
    ldkv(base + 8 + grp, b1);
    for (; base < c1; base += 16) {
        KVRegs n0; ldkv(base + 16 + grp, n0);
        step(b0, base + grp);
        b0 = n0;
        if (base + 8 < c1) {               // warp-uniform
            KVRegs n1; ldkv(base + 24 + grp, n1);
            step(b1, base + 8 + grp);
            b1 = n1;
        }
    }

    // merge the two 16-lane groups within the warp
    {
        const float mo = __shfl_xor_sync(0xffffffffu, m, 16);
        const float M  = fmaxf(m, mo);
        const float sc = (m == M) ? 1.f : __expf(m - M);   // handles -inf==-inf
        const u64 sc2 = pack2(sc);
#pragma unroll
        for (int g = 0; g < GG; g++) {
            const float ls = l[g] * sc;
            l[g] = ls + __shfl_xor_sync(0xffffffffu, ls, 16);
#pragma unroll
            for (int p = 0; p < 4; p++) {
                u64 t; MUL2(t, acc[g][p], sc2);
                u64 o = __shfl_xor_sync(0xffffffffu, t, 16);
                ADD2(acc[g][p], t, o);
            }
        }
        m = M;
    }

    // one partial per warp (PARTS = NSPLIT*WARPS = 32)
    const int part = split * WARPS + warp;
    if (lane < 16) {
        float* outp = g_acc + (size_t)(((b*KVHH + kvh)*PARTS + part)*GG) * DD + lig*4;
#pragma unroll
        for (int g = 0; g < GG; g++) {
            *(ulonglong2*)(outp + g*DD)      = make_ulonglong2(acc[g][0], acc[g][1]);
            *(ulonglong2*)(outp + g*DD + 64) = make_ulonglong2(acc[g][2], acc[g][3]);
        }
    }
    if (lane == 0) {
        const int mi = ((b*KVHH + kvh)*PARTS + part) * MLSZ;
        g_ml[mi + 0] = m;
#pragma unroll
        for (int g = 0; g < GG; g++) g_ml[mi + 1 + g] = l[g];
    }
}

__global__ void __launch_bounds__(256)
pa_combine(float* __restrict__ out)
{
    const int bh   = blockIdx.x;          // b*H + h
    const int b    = bh / HH;
    const int h    = bh % HH;
    const int kvh  = h / GG;
    const int g    = h % GG;
    const int half = threadIdx.x >> 7;    // 0/1: which 16 partials
    const int d    = threadIdx.x & 127;   // dim

    __shared__ float sm[PARTS], sl[PARTS];
    __shared__ float sO[DD], sL[DD];
    if (threadIdx.x < PARTS) {
        const int mi = ((b*KVHH + kvh)*PARTS + threadIdx.x) * MLSZ;
        sm[threadIdx.x] = g_ml[mi + 0];
        sl[threadIdx.x] = g_ml[mi + 1 + g];   // this head's partition function
    }
    __syncthreads();

    float M = -CUDART_INF_F;
#pragma unroll
    for (int p = 0; p < PARTS; p++) M = fmaxf(M, sm[p]);

    // each half: 16 partials, 4 independent chains
    const int p0 = half * (PARTS/2);
    float L0 = 0.f, L1 = 0.f, L2 = 0.f, L3 = 0.f;
    float o0 = 0.f, o1 = 0.f, o2 = 0.f, o3 = 0.f;
    const float* base = g_acc + (size_t)((b*KVHH + kvh)*PARTS) * GG * DD + g*DD + d;
#pragma unroll
    for (int p = p0; p < p0 + PARTS/2; p += 4) {
        const float e0 = __expf(sm[p+0] - M);
        const float e1 = __expf(sm[p+1] - M);
        const float e2 = __expf(sm[p+2] - M);
        const float e3 = __expf(sm[p+3] - M);
        L0 += e0 * sl[p+0];  o0 += e0 * base[(size_t)(p+0) * GG * DD];
        L1 += e1 * sl[p+1];  o1 += e1 * base[(size_t)(p+1) * GG * DD];
        L2 += e2 * sl[p+2];  o2 += e2 * base[(size_t)(p+2) * GG * DD];
        L3 += e3 * sl[p+3];  o3 += e3 * base[(size_t)(p+3) * GG * DD];
    }
    const float oh = (o0 + o1) + (o2 + o3);
    const float Lh = (L0 + L1) + (L2 + L3);

    if (half == 1) { sO[d] = oh; sL[d] = Lh; }
    __syncthreads();
    if (half == 0)
        out[(size_t)bh * DD + d] = (oh + sO[d]) / (Lh + sL[d]);
}

extern "C" void kernel_launch(void* const* d_in, const int* in_sizes, int n_in,
                              void* d_out, int out_size)
{
    const float* q   = (const float*)d_in[0];
    const float* kpg = (const float*)d_in[1];
    const float* vpg = (const float*)d_in[2];
    const int*   len = (const int*)  d_in[3];
    const int*   pid = (const int*)  d_in[4];
    float* out = (float*)d_out;

    // nop launches shift ncu's "-s 5" capture onto pa_partial (launch idx 5)
    pa_nop<<<1, 32>>>();
    pa_partial<<<BB*KVHH*NSPLIT, WARPS*32>>>(q, kpg, vpg, len, pid);
    pa_combine<<<BB*HH, 256>>>(out);
    pa_nop<<<1, 32>>>();
}